// round 5
// baseline (speedup 1.0000x reference)
#include <cuda_runtime.h>

// Problem constants (fixed shapes from the reference):
//   points          (B, N, 3)  f32
//   point_features  (B, N, C)  f32
//   boxes3d         (B, M, 7)  f32  (cx, cy, cz_bottom, dx, dy, dz, rz)
// Outputs (concatenated into d_out):
//   pooled_features (B, M, S, 3+C) f32
//   pooled_empty_flag (B, M)       written as 0.0/1.0 at the tail
#define BB    4
#define NPTS  16384
#define MBOX  128
#define CFEAT 128
#define SSAMP 512
#define ROW   (3 + CFEAT)   // 131

__global__ __launch_bounds__(256)
void roipool3d_kernel(const float* __restrict__ points,
                      const float* __restrict__ feats,
                      const float* __restrict__ boxes,
                      float* __restrict__ out,
                      float* __restrict__ flags)   // may be nullptr
{
    __shared__ int s_idx[SSAMP];
    __shared__ int s_wcnt[8];

    const int box_id = blockIdx.x;           // b * MBOX + m
    const int b      = box_id / MBOX;
    const int tid    = threadIdx.x;
    const int wid    = tid >> 5;
    const int lane   = tid & 31;

    // ---- box parameters (all threads load; tiny, L1-hot) ----
    const float* bx = boxes + box_id * 7;
    const float cx  = bx[0];
    const float cy  = bx[1];
    const float dxh = 0.5f * bx[3];
    const float dyh = 0.5f * bx[4];
    const float dzh = 0.5f * bx[5];
    const float cz  = bx[2] + dzh;           // bottom center -> geometric center
    const float rz  = bx[6];
    const float cosa = cosf(-rz);            // match reference: cos(-rz), sin(-rz)
    const float sina = sinf(-rz);

    const float* pts = points + (size_t)b * NPTS * 3;

    // ---- Phase A: ordered stream compaction of in-box point indices ----
    int count = 0;
    for (int base = 0; base < NPTS; base += 256) {
        const int n = base + tid;
        const float px = pts[n * 3 + 0];
        const float py = pts[n * 3 + 1];
        const float pz = pts[n * 3 + 2];
        const float sx = px - cx;
        const float sy = py - cy;
        const float lx = sx * cosa - sy * sina;
        const float ly = sx * sina + sy * cosa;
        const bool in =
            (fabsf(pz - cz) <= dzh) &&
            (lx > -dxh) && (lx < dxh) &&
            (ly > -dyh) && (ly < dyh);

        const unsigned bal = __ballot_sync(0xffffffffu, in);
        if (lane == 0) s_wcnt[wid] = __popc(bal);
        __syncthreads();

        int wb = count;                       // ordered base for this warp
        #pragma unroll
        for (int w = 0; w < 8; w++) {
            const int c = s_wcnt[w];
            if (w < wid) wb += c;
            count += c;                       // identical across all threads
        }
        if (in) {
            const int pos = wb + __popc(bal & ((1u << lane) - 1u));
            if (pos < SSAMP) s_idx[pos] = n;
        }
        __syncthreads();                      // protect s_wcnt for next iter
        if (count >= SSAMP) break;            // j % cnt == j for cnt >= S
    }

    const int cnt = count < SSAMP ? count : SSAMP;
    float* ob = out + (size_t)box_id * (SSAMP * ROW);

    // ---- Phase B: write pooled output ----
    if (cnt == 0) {
        // d_out is poisoned; must write zeros. Per-box region is 16B-aligned.
        float4 z = make_float4(0.f, 0.f, 0.f, 0.f);
        float4* o4 = reinterpret_cast<float4*>(ob);
        const int n4 = (SSAMP * ROW) / 4;     // 67072 / 4 = 16768 exactly
        for (int i = tid; i < n4; i += 256) o4[i] = z;
        if (tid == 0 && flags != nullptr) flags[box_id] = 1.0f;
        return;
    }

    const float* fb = feats + (size_t)b * NPTS * CFEAT;
    // warp-per-row: each warp handles rows s = wid, wid+8, ...
    for (int s = wid; s < SSAMP; s += 8) {
        const int idx = s_idx[s % cnt];
        const float* frow = fb + (size_t)idx * CFEAT;
        float* orow = ob + s * ROW;
        #pragma unroll
        for (int k = 0; k < 4; k++) {
            const int c = lane + k * 32;      // columns 0..127
            const float v = (c < 3) ? pts[idx * 3 + c] : frow[c - 3];
            orow[c] = v;
        }
        if (lane < 3) orow[128 + lane] = frow[125 + lane];  // columns 128..130
    }
    if (tid == 0 && flags != nullptr) flags[box_id] = 0.0f;
}

extern "C" void kernel_launch(void* const* d_in, const int* in_sizes, int n_in,
                              void* d_out, int out_size)
{
    const float* points = (const float*)d_in[0];   // (B, N, 3)
    const float* feats  = (const float*)d_in[1];   // (B, N, C)
    const float* boxes  = (const float*)d_in[2];   // (B, M, 7)

    float* out = (float*)d_out;
    const size_t feat_elems = (size_t)BB * MBOX * SSAMP * ROW;   // 34,340,864
    float* flags = nullptr;
    if ((size_t)out_size >= feat_elems + (size_t)BB * MBOX)
        flags = out + feat_elems;

    roipool3d_kernel<<<BB * MBOX, 256>>>(points, feats, boxes, out, flags);
}

// round 8
// speedup vs baseline: 1.1236x; 1.1236x over previous
#include <cuda_runtime.h>

// Shapes (fixed):
//   points          (B, N, 3)  f32
//   point_features  (B, N, C)  f32
//   boxes3d         (B, M, 7)  f32  (cx, cy, cz_bottom, dx, dy, dz, rz)
// Output d_out:
//   pooled_features (B, M, S, 3+C) f32   [+ pooled_empty_flag (B,M) at tail if room]
#define BB    4
#define NPTS  16384
#define MBOX  128
#define CFEAT 128
#define SSAMP 512
#define ROW   (3 + CFEAT)        // 131
#define NBOX  (BB * MBOX)        // 512
#define RND   1024               // points per scan round (4 chunks of 256)

// Cross-kernel scratch (device globals — no allocation).
__device__ int g_idx[NBOX * SSAMP];   // ordered in-box point indices per box
__device__ int g_cnt[NBOX];           // in-box count (uncapped, then capped on read)

// ============================ Kernel 1: scan ============================
// One CTA per box. Ordered stream compaction of in-box point indices.
__global__ __launch_bounds__(256)
void scan_kernel(const float* __restrict__ points,
                 const float* __restrict__ boxes)
{
    __shared__ float s_pts[RND * 3];   // 12 KB staged points
    __shared__ int   s_wcnt[32];       // per (chunk, warp) counts, chunk-major

    const int box_id = blockIdx.x;
    const int b      = box_id / MBOX;
    const int tid    = threadIdx.x;
    const int wid    = tid >> 5;
    const int lane   = tid & 31;

    const float* bx = boxes + box_id * 7;
    const float cx  = bx[0];
    const float cy  = bx[1];
    const float dxh = 0.5f * bx[3];
    const float dyh = 0.5f * bx[4];
    const float dzh = 0.5f * bx[5];
    const float cz  = bx[2] + dzh;
    const float rz  = bx[6];
    const float cosa = cosf(-rz);      // replicate reference op order
    const float sina = sinf(-rz);

    const float*  pts  = points + (size_t)b * NPTS * 3;
    int* __restrict__ my_idx = g_idx + box_id * SSAMP;

    int count = 0;
    for (int base = 0; base < NPTS; base += RND) {
        __syncthreads();               // protect s_pts / s_wcnt reuse
        // --- stage 1024 points: 768 coalesced float4 loads ---
        const float4* src4 = reinterpret_cast<const float4*>(pts + base * 3);
        float4* dst4 = reinterpret_cast<float4*>(s_pts);
        #pragma unroll
        for (int i = 0; i < 3; i++) dst4[tid + i * 256] = src4[tid + i * 256];
        __syncthreads();

        // --- test 4 chunks, one ballot each ---
        unsigned bal[4];
        #pragma unroll
        for (int k = 0; k < 4; k++) {
            const int p  = k * 256 + tid;          // local point id
            const float px = s_pts[p * 3 + 0];
            const float py = s_pts[p * 3 + 1];
            const float pz = s_pts[p * 3 + 2];
            const float sx = px - cx;
            const float sy = py - cy;
            const float lx = sx * cosa - sy * sina;
            const float ly = sx * sina + sy * cosa;
            const bool in =
                (fabsf(pz - cz) <= dzh) &&
                (lx > -dxh) && (lx < dxh) &&
                (ly > -dyh) && (ly < dyh);
            bal[k] = __ballot_sync(0xffffffffu, in);
            if (lane == 0) s_wcnt[k * 8 + wid] = __popc(bal[k]);
        }
        __syncthreads();

        // --- ordered prefix over the 32 (chunk, warp) groups ---
        int base_k[4];
        int total = count;
        #pragma unroll
        for (int j = 0; j < 32; j++) {
            const int c = s_wcnt[j];
            #pragma unroll
            for (int k = 0; k < 4; k++)
                if (j == k * 8 + wid) base_k[k] = total;
            total += c;
        }
        // --- emit ---
        #pragma unroll
        for (int k = 0; k < 4; k++) {
            if ((bal[k] >> lane) & 1u) {
                const int pos = base_k[k] + __popc(bal[k] & ((1u << lane) - 1u));
                if (pos < SSAMP) my_idx[pos] = base + k * 256 + tid;
            }
        }
        count = total;
        if (count >= SSAMP) break;     // j % cnt == j for cnt >= S
    }
    if (tid == 0) g_cnt[box_id] = count;
}

// ============================ Kernel 2: gather + write ============================
// One CTA per (box, quarter): 128 output rows each. grid = 2048.
__global__ __launch_bounds__(256)
void gather_kernel(const float* __restrict__ points,
                   const float* __restrict__ feats,
                   float* __restrict__ out,
                   float* __restrict__ flags)
{
    const int box_id = blockIdx.x >> 2;
    const int q      = blockIdx.x & 3;
    const int b      = box_id / MBOX;
    const int tid    = threadIdx.x;
    const int wid    = tid >> 5;
    const int lane   = tid & 31;

    int cnt = g_cnt[box_id];
    if (cnt > SSAMP) cnt = SSAMP;

    float* ob  = out + (size_t)box_id * (SSAMP * ROW);
    float* oq  = ob + q * 128 * ROW;               // this quarter: 16768 floats, 16B-aligned

    if (cnt == 0) {
        // d_out is poisoned — must write zeros. 16768/4 = 4192 float4s.
        const float4 z = make_float4(0.f, 0.f, 0.f, 0.f);
        float4* o4 = reinterpret_cast<float4*>(oq);
        for (int i = tid; i < 4192; i += 256) __stcs(&o4[i], z);
        if (q == 0 && tid == 0 && flags != nullptr) flags[box_id] = 1.0f;
        return;
    }

    const float* pts = points + (size_t)b * NPTS * 3;
    const float* fb  = feats  + (size_t)b * NPTS * CFEAT;
    const int* my_idx = g_idx + box_id * SSAMP;
    const int s0 = q * 128;

    // warp-per-row, 16 contiguous rows per warp
    for (int i = 0; i < 16; i++) {
        const int s   = s0 + wid * 16 + i;
        const int idx = my_idx[s % cnt];           // L1-hot, uniform per warp
        const float4 f = reinterpret_cast<const float4*>(fb + (size_t)idx * CFEAT)[lane];
        float* orow = ob + s * ROW;
        __stcs(orow + 3 + 4 * lane + 0, f.x);
        __stcs(orow + 3 + 4 * lane + 1, f.y);
        __stcs(orow + 3 + 4 * lane + 2, f.z);
        __stcs(orow + 3 + 4 * lane + 3, f.w);
        if (lane < 3) __stcs(orow + lane, pts[idx * 3 + lane]);
    }
    if (q == 0 && tid == 0 && flags != nullptr) flags[box_id] = 0.0f;
}

extern "C" void kernel_launch(void* const* d_in, const int* in_sizes, int n_in,
                              void* d_out, int out_size)
{
    const float* points = (const float*)d_in[0];   // (B, N, 3)
    const float* feats  = (const float*)d_in[1];   // (B, N, C)
    const float* boxes  = (const float*)d_in[2];   // (B, M, 7)

    float* out = (float*)d_out;
    const size_t feat_elems = (size_t)NBOX * SSAMP * ROW;   // 34,340,864
    float* flags = nullptr;
    if ((size_t)out_size >= feat_elems + (size_t)NBOX)
        flags = out + feat_elems;

    scan_kernel<<<NBOX, 256>>>(points, boxes);
    gather_kernel<<<NBOX * 4, 256>>>(points, feats, out, flags);
}

// round 9
// speedup vs baseline: 1.4011x; 1.2470x over previous
#include <cuda_runtime.h>

// Shapes (fixed):
//   points          (B, N, 3)  f32
//   point_features  (B, N, C)  f32
//   boxes3d         (B, M, 7)  f32  (cx, cy, cz_bottom, dx, dy, dz, rz)
// Output d_out:
//   pooled_features (B, M, S, 3+C) f32   [+ pooled_empty_flag (B,M) at tail if room]
#define BB    4
#define NPTS  16384
#define MBOX  128
#define CFEAT 128
#define SSAMP 512
#define ROW   (3 + CFEAT)        // 131
#define NBOX  (BB * MBOX)        // 512
#define NSEG  8                  // segments per box
#define SEGPTS (NPTS / NSEG)     // 2048 points per segment
#define RND   1024               // points per scan round

// Cross-kernel scratch (device globals — no allocation).
// Per (box, segment): ordered in-box local ranks (first 512) + uncapped count.
__device__ int g_seg_idx[NBOX * NSEG * SSAMP];   // 8 MB
__device__ int g_scnt[NBOX * NSEG];

// ============================ Kernel 1: segmented scan ============================
// One CTA per (box, segment). 2 rounds of 1024 points each.
__global__ __launch_bounds__(256)
void scan_kernel(const float* __restrict__ points,
                 const float* __restrict__ boxes)
{
    __shared__ float s_pts[RND * 3];   // 12 KB staged points
    __shared__ int   s_wcnt[32];       // per (chunk, warp) counts, chunk-major

    const int seg_id = blockIdx.x;         // box_id * NSEG + seg
    const int box_id = seg_id >> 3;
    const int seg    = seg_id & 7;
    const int b      = box_id / MBOX;
    const int tid    = threadIdx.x;
    const int wid    = tid >> 5;
    const int lane   = tid & 31;

    const float* bx = boxes + box_id * 7;
    const float cx  = bx[0];
    const float cy  = bx[1];
    const float dxh = 0.5f * bx[3];
    const float dyh = 0.5f * bx[4];
    const float dzh = 0.5f * bx[5];
    const float cz  = bx[2] + dzh;
    const float rz  = bx[6];
    const float cosa = cosf(-rz);          // replicate reference op order
    const float sina = sinf(-rz);

    const float* pts = points + (size_t)b * NPTS * 3 + (size_t)seg * SEGPTS * 3;
    int* __restrict__ my_idx = g_seg_idx + seg_id * SSAMP;

    int count = 0;
    #pragma unroll
    for (int base = 0; base < SEGPTS; base += RND) {
        if (base) __syncthreads();         // protect s_pts / s_wcnt reuse
        // --- stage 1024 points: 768 coalesced float4 loads ---
        const float4* src4 = reinterpret_cast<const float4*>(pts + base * 3);
        float4* dst4 = reinterpret_cast<float4*>(s_pts);
        #pragma unroll
        for (int i = 0; i < 3; i++) dst4[tid + i * 256] = src4[tid + i * 256];
        __syncthreads();

        // --- test 4 chunks, one ballot each ---
        unsigned bal[4];
        #pragma unroll
        for (int k = 0; k < 4; k++) {
            const int p  = k * 256 + tid;
            const float px = s_pts[p * 3 + 0];
            const float py = s_pts[p * 3 + 1];
            const float pz = s_pts[p * 3 + 2];
            const float sx = px - cx;
            const float sy = py - cy;
            const float lx = sx * cosa - sy * sina;
            const float ly = sx * sina + sy * cosa;
            const bool in =
                (fabsf(pz - cz) <= dzh) &&
                (lx > -dxh) && (lx < dxh) &&
                (ly > -dyh) && (ly < dyh);
            bal[k] = __ballot_sync(0xffffffffu, in);
            if (lane == 0) s_wcnt[k * 8 + wid] = __popc(bal[k]);
        }
        __syncthreads();

        // --- ordered prefix over the 32 (chunk, warp) groups ---
        int base_k[4];
        int total = count;
        #pragma unroll
        for (int j = 0; j < 32; j++) {
            const int c = s_wcnt[j];
            #pragma unroll
            for (int k = 0; k < 4; k++)
                if (j == k * 8 + wid) base_k[k] = total;
            total += c;
        }
        // --- emit (segment-local point index; global index reconstructed later) ---
        #pragma unroll
        for (int k = 0; k < 4; k++) {
            if ((bal[k] >> lane) & 1u) {
                const int pos = base_k[k] + __popc(bal[k] & ((1u << lane) - 1u));
                if (pos < SSAMP) my_idx[pos] = seg * SEGPTS + base + k * 256 + tid;
            }
        }
        count = total;
    }
    if (tid == 0) g_scnt[seg_id] = count;
}

// ============================ Kernel 2: gather + write ============================
// One CTA per (box, quarter): 128 output rows. Smem-staged tiles -> aligned STG.128.
__global__ __launch_bounds__(256)
void gather_kernel(const float* __restrict__ points,
                   const float* __restrict__ feats,
                   float* __restrict__ out,
                   float* __restrict__ flags)
{
    __shared__ float s_tile[32 * ROW];     // 32 rows x 131 floats = 16768 B

    const int box_id = blockIdx.x >> 2;
    const int q      = blockIdx.x & 3;
    const int b      = box_id / MBOX;
    const int tid    = threadIdx.x;
    const int wid    = tid >> 5;
    const int lane   = tid & 31;

    // --- per-box segment prefix (8 small L2-hot loads, all threads) ---
    int pre[NSEG + 1];
    pre[0] = 0;
    #pragma unroll
    for (int k = 0; k < NSEG; k++)
        pre[k + 1] = pre[k] + g_scnt[box_id * NSEG + k];
    const int total = pre[NSEG];
    const int cnt = total < SSAMP ? total : SSAMP;

    float* ob = out + (size_t)box_id * (SSAMP * ROW);
    float* oq = ob + q * 128 * ROW;        // 16768 floats, 16B-aligned

    if (cnt == 0) {
        const float4 z = make_float4(0.f, 0.f, 0.f, 0.f);
        float4* o4 = reinterpret_cast<float4*>(oq);
        for (int i = tid; i < 4192; i += 256) __stcs(&o4[i], z);
        if (q == 0 && tid == 0 && flags != nullptr) flags[box_id] = 1.0f;
        return;
    }

    const float* pts = points + (size_t)b * NPTS * 3;
    const float* fb  = feats  + (size_t)b * NPTS * CFEAT;
    const int* seg_base = g_seg_idx + box_id * NSEG * SSAMP;
    const int s0 = q * 128;

    #pragma unroll
    for (int t = 0; t < 4; t++) {          // 4 tiles of 32 rows
        if (t) __syncthreads();            // previous tile fully drained
        // --- gather 32 rows into smem (warp w handles rows w*4..w*4+3) ---
        #pragma unroll
        for (int i = 0; i < 4; i++) {
            const int r = wid * 4 + i;             // local row 0..31
            const int s = s0 + t * 32 + r;         // global sample 0..511
            const int j = s % cnt;                 // global in-box rank
            // locate segment containing rank j
            int k = 0;
            #pragma unroll
            for (int kk = 1; kk < NSEG; kk++)
                if (j >= pre[kk]) k = kk;
            const int idx = seg_base[k * SSAMP + (j - pre[k])];
            const float4 f = reinterpret_cast<const float4*>(fb + (size_t)idx * CFEAT)[lane];
            float* srow = s_tile + r * ROW;
            srow[3 + 4 * lane + 0] = f.x;
            srow[3 + 4 * lane + 1] = f.y;
            srow[3 + 4 * lane + 2] = f.z;
            srow[3 + 4 * lane + 3] = f.w;
            if (lane < 3) srow[lane] = pts[idx * 3 + lane];
        }
        __syncthreads();
        // --- aligned streaming write: 4192 floats = 1048 float4 ---
        const float4* s4 = reinterpret_cast<const float4*>(s_tile);
        float4* o4 = reinterpret_cast<float4*>(oq + t * 32 * ROW);
        for (int i = tid; i < 1048; i += 256) __stcs(&o4[i], s4[i]);
    }
    if (q == 0 && tid == 0 && flags != nullptr) flags[box_id] = 0.0f;
}

extern "C" void kernel_launch(void* const* d_in, const int* in_sizes, int n_in,
                              void* d_out, int out_size)
{
    const float* points = (const float*)d_in[0];   // (B, N, 3)
    const float* feats  = (const float*)d_in[1];   // (B, N, C)
    const float* boxes  = (const float*)d_in[2];   // (B, M, 7)

    float* out = (float*)d_out;
    const size_t feat_elems = (size_t)NBOX * SSAMP * ROW;   // 34,340,864
    float* flags = nullptr;
    if ((size_t)out_size >= feat_elems + (size_t)NBOX)
        flags = out + feat_elems;

    scan_kernel<<<NBOX * NSEG, 256>>>(points, boxes);
    gather_kernel<<<NBOX * 4, 256>>>(points, feats, out, flags);
}

// round 10
// speedup vs baseline: 1.4472x; 1.0329x over previous
#include <cuda_runtime.h>

// Shapes (fixed):
//   points          (B, N, 3)  f32
//   point_features  (B, N, C)  f32
//   boxes3d         (B, M, 7)  f32  (cx, cy, cz_bottom, dx, dy, dz, rz)
// Output d_out:
//   pooled_features (B, M, S, 3+C) f32   [+ pooled_empty_flag (B,M) at tail if room]
#define BB    4
#define NPTS  16384
#define MBOX  128
#define CFEAT 128
#define SSAMP 512
#define ROW   (3 + CFEAT)        // 131
#define NBOX  (BB * MBOX)        // 512
#define NSEG  16                 // segments per box
#define SEGPTS (NPTS / NSEG)     // 1024 points per segment

// Cross-kernel scratch (device globals — no allocation).
// Per (box, segment): ordered in-box local indices (first 512 only — a global
// rank j < S=512 implies local rank <= j < 512, so 512 slots always suffice).
__device__ int g_seg_idx[NBOX * NSEG * SSAMP];   // 16 MB
__device__ int g_scnt[NBOX * NSEG];

// ============================ Kernel 1: segmented scan ============================
// One CTA per (box, segment): exactly one 1024-point round, 2 barriers.
__global__ __launch_bounds__(256)
void scan_kernel(const float* __restrict__ points,
                 const float* __restrict__ boxes)
{
    __shared__ float s_pts[SEGPTS * 3];    // 12 KB staged points
    __shared__ int   s_wcnt[32];           // per (chunk, warp) counts, chunk-major

    const int seg_id = blockIdx.x;         // box_id * NSEG + seg
    const int box_id = seg_id >> 4;
    const int seg    = seg_id & 15;
    const int b      = box_id / MBOX;
    const int tid    = threadIdx.x;
    const int wid    = tid >> 5;
    const int lane   = tid & 31;

    const float* bx = boxes + box_id * 7;
    const float cx  = bx[0];
    const float cy  = bx[1];
    const float dxh = 0.5f * bx[3];
    const float dyh = 0.5f * bx[4];
    const float dzh = 0.5f * bx[5];
    const float cz  = bx[2] + dzh;
    const float rz  = bx[6];
    const float cosa = cosf(-rz);          // replicate reference op order
    const float sina = sinf(-rz);

    const float* pts = points + (size_t)b * NPTS * 3 + (size_t)seg * SEGPTS * 3;
    int* __restrict__ my_idx = g_seg_idx + seg_id * SSAMP;

    // --- stage 1024 points: 768 coalesced float4 loads ---
    const float4* src4 = reinterpret_cast<const float4*>(pts);
    float4* dst4 = reinterpret_cast<float4*>(s_pts);
    #pragma unroll
    for (int i = 0; i < 3; i++) dst4[tid + i * 256] = src4[tid + i * 256];
    __syncthreads();

    // --- test 4 chunks of 256, one ballot each ---
    unsigned bal[4];
    #pragma unroll
    for (int k = 0; k < 4; k++) {
        const int p  = k * 256 + tid;
        const float px = s_pts[p * 3 + 0];
        const float py = s_pts[p * 3 + 1];
        const float pz = s_pts[p * 3 + 2];
        const float sx = px - cx;
        const float sy = py - cy;
        const float lx = sx * cosa - sy * sina;
        const float ly = sx * sina + sy * cosa;
        const bool in =
            (fabsf(pz - cz) <= dzh) &&
            (lx > -dxh) && (lx < dxh) &&
            (ly > -dyh) && (ly < dyh);
        bal[k] = __ballot_sync(0xffffffffu, in);
        if (lane == 0) s_wcnt[k * 8 + wid] = __popc(bal[k]);
    }
    __syncthreads();

    // --- ordered prefix over the 32 (chunk, warp) groups ---
    int base_k[4];
    int total = 0;
    #pragma unroll
    for (int j = 0; j < 32; j++) {
        const int c = s_wcnt[j];
        #pragma unroll
        for (int k = 0; k < 4; k++)
            if (j == k * 8 + wid) base_k[k] = total;
        total += c;
    }
    // --- emit segment-local ordered indices (global point id) ---
    #pragma unroll
    for (int k = 0; k < 4; k++) {
        if ((bal[k] >> lane) & 1u) {
            const int pos = base_k[k] + __popc(bal[k] & ((1u << lane) - 1u));
            if (pos < SSAMP) my_idx[pos] = seg * SEGPTS + k * 256 + tid;
        }
    }
    if (tid == 0) g_scnt[seg_id] = total;
}

// ============================ Kernel 2: gather + write ============================
// One CTA per (box, quarter): 128 output rows. Index-resolve prologue, then
// conflict-free smem tiles swept out as aligned STG.128 streaming stores.
__global__ __launch_bounds__(256)
void gather_kernel(const float* __restrict__ points,
                   const float* __restrict__ feats,
                   float* __restrict__ out,
                   float* __restrict__ flags)
{
    __shared__ float s_tile[32 * ROW];     // 32 rows x 131 floats = 16768 B
    __shared__ int   s_rowidx[128];        // resolved point index per output row
    __shared__ int   s_cnt;

    const int box_id = blockIdx.x >> 2;
    const int q      = blockIdx.x & 3;
    const int b      = box_id / MBOX;
    const int tid    = threadIdx.x;
    const int wid    = tid >> 5;
    const int lane   = tid & 31;

    // --- prologue: resolve indices once per row (threads 0..127) ---
    if (tid < 128) {
        const int* sc = g_scnt + box_id * NSEG;
        int pre[NSEG + 1];
        pre[0] = 0;
        #pragma unroll
        for (int k = 0; k < NSEG; k++) pre[k + 1] = pre[k] + sc[k];
        int cnt = pre[NSEG];
        if (cnt > SSAMP) cnt = SSAMP;
        if (tid == 0) s_cnt = cnt;
        if (cnt > 0) {
            const int s = q * 128 + tid;
            const int j = s % cnt;                 // global in-box rank (< 512)
            int k = 0;
            #pragma unroll
            for (int kk = 1; kk < NSEG; kk++)
                if (j >= pre[kk]) k = kk;
            s_rowidx[tid] = g_seg_idx[(box_id * NSEG + k) * SSAMP + (j - pre[k])];
        }
    }
    __syncthreads();
    const int cnt = s_cnt;

    float* ob = out + (size_t)box_id * (SSAMP * ROW);
    float* oq = ob + q * 128 * ROW;        // 16768 floats, 16B-aligned

    if (cnt == 0) {
        const float4 z = make_float4(0.f, 0.f, 0.f, 0.f);
        float4* o4 = reinterpret_cast<float4*>(oq);
        for (int i = tid; i < 4192; i += 256) __stcs(&o4[i], z);
        if (q == 0 && tid == 0 && flags != nullptr) flags[box_id] = 1.0f;
        return;
    }

    const float* pts = points + (size_t)b * NPTS * 3;
    const float* fb  = feats  + (size_t)b * NPTS * CFEAT;

    #pragma unroll
    for (int t = 0; t < 4; t++) {          // 4 tiles of 32 rows
        if (t) __syncthreads();            // previous tile fully drained
        // --- gather 32 rows into smem; warp w handles rows w*4..w*4+3 ---
        #pragma unroll
        for (int i = 0; i < 4; i++) {
            const int r   = wid * 4 + i;           // local row in tile
            const int idx = s_rowidx[t * 32 + r];  // broadcast LDS
            const float* frow = fb + (size_t)idx * CFEAT;
            float* srow = s_tile + r * ROW;
            // coalesced element map: lane l handles columns l, 32+l, 64+l, 96+l
            // -> STS bank (l+3)%32, conflict-free
            #pragma unroll
            for (int p = 0; p < 4; p++)
                srow[3 + 32 * p + lane] = frow[32 * p + lane];
            if (lane < 3) srow[lane] = pts[idx * 3 + lane];
        }
        __syncthreads();
        // --- aligned streaming write: 4192 floats = 1048 float4 ---
        const float4* s4 = reinterpret_cast<const float4*>(s_tile);
        float4* o4 = reinterpret_cast<float4*>(oq + t * 32 * ROW);
        for (int i = tid; i < 1048; i += 256) __stcs(&o4[i], s4[i]);
    }
    if (q == 0 && tid == 0 && flags != nullptr) flags[box_id] = 0.0f;
}

extern "C" void kernel_launch(void* const* d_in, const int* in_sizes, int n_in,
                              void* d_out, int out_size)
{
    const float* points = (const float*)d_in[0];   // (B, N, 3)
    const float* feats  = (const float*)d_in[1];   // (B, N, C)
    const float* boxes  = (const float*)d_in[2];   // (B, M, 7)

    float* out = (float*)d_out;
    const size_t feat_elems = (size_t)NBOX * SSAMP * ROW;   // 34,340,864
    float* flags = nullptr;
    if ((size_t)out_size >= feat_elems + (size_t)NBOX)
        flags = out + feat_elems;

    scan_kernel<<<NBOX * NSEG, 256>>>(points, boxes);
    gather_kernel<<<NBOX * 4, 256>>>(points, feats, out, flags);
}